// round 13
// baseline (speedup 1.0000x reference)
#include <cuda_runtime.h>
#include <math.h>

// ---------------------------------------------------------------------------
// Problem constants
//   x: (8, 256, 128, 128) fp32, proj -> 512ch, cluster groups m=256 of
//   (c=64, 64x64), merge -> 256ch, GN(whole sample), MLP 512->512(gelu)->256,
//   GN, *layer_scale + x.
// ---------------------------------------------------------------------------
#define Nn   8
#define Cc   256
#define Hh   128
#define Ww   128
#define HW   16384          // 128*128
#define PIX_PER_N HW
#define GN_COUNT 4194304.0f // 256*128*128

// ------------------------- scratch (device globals) ------------------------
__device__ float g_y[256L * 64 * 64 * 64];      // proj out, [m][c][h'][w']  268MB
__device__ float g_nx[8L * 256 * 128 * 128];    // cluster out, NCHW         134MB
__device__ float g_newx[8L * 256 * 128 * 128];  // merge out, NCHW           134MB
__device__ float g_th[8L * 512 * 128 * 128];    // mlp hidden, NCHW          268MB
__device__ float g_out2[8L * 256 * 128 * 128];  // mlp out, NCHW             134MB

__device__ float g_psum0[2048], g_psq0[2048];   // per-block GN partials (merge)
__device__ float g_psum1[2048], g_psq1[2048];   // per-block GN partials (mlp1)
__device__ float g_mu0[8], g_rs0[8], g_mu1[8], g_rs1[8];

// ------------------------- packed f32x2 helpers ----------------------------
__device__ __forceinline__ void fma2(unsigned long long &d,
                                     unsigned long long a,
                                     unsigned long long b) {
    asm("fma.rn.f32x2 %0, %1, %2, %0;" : "+l"(d) : "l"(a), "l"(b));
}
__device__ __forceinline__ unsigned long long pk2(float x, float y) {
    unsigned long long r;
    asm("mov.b64 %0, {%1, %2};" : "=l"(r) : "f"(x), "f"(y));
    return r;
}
__device__ __forceinline__ float2 upk2(unsigned long long v) {
    float2 r;
    asm("mov.b64 {%0, %1}, %2;" : "=f"(r.x), "=f"(r.y) : "l"(v));
    return r;
}

// ---------------------------------------------------------------------------
// Generic tiled GEMM over pixels: out[o, p] = sum_k W[o,k] * X[k, p] + bias[o]
// Tile: 128 outputs x 128 pixels (one W-row of the image) x KT=16.
// 256 threads, 8x8 per thread via packed f32x2 FMAs.
// MODE 0: proj  (W o-major 512x256, X = x NCHW,   out -> g_y permuted)
// MODE 1: merge (W o-major 256x256, X = g_nx,     out -> g_newx + GN partials)
// MODE 2: mlp0  (W k-major 512x512, X = concat(x, gn0(g_newx)), out gelu->g_th)
// MODE 3: mlp1  (W k-major 512x256, X = g_th,     out -> g_out2 + GN partials)
// ---------------------------------------------------------------------------
template <int KDIM, int MODE>
__global__ __launch_bounds__(256) void k_gemm(const float* __restrict__ B_in,
                                              const float* __restrict__ Wm,
                                              const float* __restrict__ bias,
                                              const float* __restrict__ aux0,
                                              const float* __restrict__ aux1) {
    constexpr int KT = 16;
    __shared__ float Wt[KT][128];
    __shared__ float Xt[KT][128];
    __shared__ float rA[8], rB[8];

    const int Hi = blockIdx.x;
    const int o0 = blockIdx.y * 128;
    const int n  = blockIdx.z;
    const int tid = threadIdx.x;
    const int tx = tid & 15, ty = tid >> 4;
    const int rowoff = Hi * 128;

    float mu0 = 0.f, rs0 = 0.f;
    if (MODE == 2) { mu0 = g_mu0[n]; rs0 = g_rs0[n]; }

    unsigned long long acc2[8][4];
#pragma unroll
    for (int i = 0; i < 8; i++)
#pragma unroll
        for (int j = 0; j < 4; j++) acc2[i][j] = 0ull;

    for (int c0 = 0; c0 < KDIM; c0 += KT) {
        // ---- load weight tile ----
        if (MODE == 0 || MODE == 1) {          // o-major: W[o*KDIM + k]
#pragma unroll
            for (int i = 0; i < 2; i++) {
                int e = tid + i * 256;          // 512 float4
                int o = e >> 2, kq = (e & 3) * 4;
                float4 v = *(const float4*)&Wm[(long)(o0 + o) * KDIM + c0 + kq];
                Wt[kq + 0][o] = v.x; Wt[kq + 1][o] = v.y;
                Wt[kq + 2][o] = v.z; Wt[kq + 3][o] = v.w;
            }
        } else {                                // k-major: W[k*OD + o]
            constexpr int OD = (MODE == 2) ? 512 : 256;
#pragma unroll
            for (int i = 0; i < 2; i++) {
                int e = tid + i * 256;
                int r = e >> 5, c4 = (e & 31) * 4;
                *(float4*)&Xt[0][0]; // no-op keep compiler calm
                *(float4*)&Wt[r][c4] =
                    *(const float4*)&Wm[(long)(c0 + r) * OD + o0 + c4];
            }
        }
        // ---- load input tile ----
#pragma unroll
        for (int i = 0; i < 2; i++) {
            int e = tid + i * 256;
            int r = e >> 5, c4 = (e & 31) * 4;
            int ch = c0 + r;
            float4 v;
            if (MODE == 0) {
                v = *(const float4*)&B_in[(long)(n * 256 + ch) * HW + rowoff + c4];
            } else if (MODE == 1) {
                v = *(const float4*)&g_nx[(long)(n * 256 + ch) * HW + rowoff + c4];
            } else if (MODE == 3) {
                v = *(const float4*)&g_th[(long)(n * 512 + ch) * HW + rowoff + c4];
            } else { // MODE 2: concat(x, gn0(new_x))
                if (ch < 256) {
                    v = *(const float4*)&B_in[(long)(n * 256 + ch) * HW + rowoff + c4];
                } else {
                    int cc = ch - 256;
                    v = *(const float4*)&g_newx[(long)(n * 256 + cc) * HW + rowoff + c4];
                    float sc = rs0 * aux0[cc];
                    float sh = aux1[cc] - mu0 * sc;
                    v.x = v.x * sc + sh; v.y = v.y * sc + sh;
                    v.z = v.z * sc + sh; v.w = v.w * sc + sh;
                }
            }
            *(float4*)&Xt[r][c4] = v;
        }
        __syncthreads();
        // ---- compute ----
#pragma unroll
        for (int k = 0; k < KT; k++) {
            float av[8];
            *(float4*)&av[0] = *(const float4*)&Wt[k][ty * 8];
            *(float4*)&av[4] = *(const float4*)&Wt[k][ty * 8 + 4];
            ulonglong2 x0 = *(const ulonglong2*)&Xt[k][tx * 8];
            ulonglong2 x1 = *(const ulonglong2*)&Xt[k][tx * 8 + 4];
            unsigned long long bp0 = x0.x, bp1 = x0.y, bp2 = x1.x, bp3 = x1.y;
#pragma unroll
            for (int i = 0; i < 8; i++) {
                unsigned long long ai = pk2(av[i], av[i]);
                fma2(acc2[i][0], ai, bp0);
                fma2(acc2[i][1], ai, bp1);
                fma2(acc2[i][2], ai, bp2);
                fma2(acc2[i][3], ai, bp3);
            }
        }
        __syncthreads();
    }

    // ---- epilogue ----
    float lsum = 0.f, lsq = 0.f;
#pragma unroll
    for (int i = 0; i < 8; i++) {
        int o = o0 + ty * 8 + i;
        float bv = bias[o];
#pragma unroll
        for (int jp = 0; jp < 4; jp++) {
            float2 pv = upk2(acc2[i][jp]);
            float vv[2] = {pv.x, pv.y};
#pragma unroll
            for (int h = 0; h < 2; h++) {
                int w = tx * 8 + jp * 2 + h;
                float v = vv[h] + bv;
                if (MODE == 0) {
                    int fc = o >> 6, cp = o & 63;
                    int fs1 = Hi >> 6, hp = Hi & 63;
                    int fs2 = w >> 6, wp = w & 63;
                    int m = ((n * 8 + fc) * 2 + fs1) * 2 + fs2;
                    g_y[(((long)m * 64 + cp) * 64 + hp) * 64 + wp] = v;
                } else if (MODE == 1) {
                    g_newx[(long)(n * 256 + o) * HW + rowoff + w] = v;
                    lsum += v; lsq += v * v;
                } else if (MODE == 2) {
                    float gv = 0.5f * v * (1.0f + erff(v * 0.70710678118654752f));
                    g_th[(long)(n * 512 + o) * HW + rowoff + w] = gv;
                } else {
                    g_out2[(long)(n * 256 + o) * HW + rowoff + w] = v;
                    lsum += v; lsq += v * v;
                }
            }
        }
    }
    if (MODE == 1 || MODE == 3) {
#pragma unroll
        for (int off = 16; off; off >>= 1) {
            lsum += __shfl_down_sync(0xffffffffu, lsum, off);
            lsq  += __shfl_down_sync(0xffffffffu, lsq,  off);
        }
        int lane = tid & 31, wp = tid >> 5;
        if (lane == 0) { rA[wp] = lsum; rB[wp] = lsq; }
        __syncthreads();
        if (tid == 0) {
            float s = 0.f, q = 0.f;
#pragma unroll
            for (int i = 0; i < 8; i++) { s += rA[i]; q += rB[i]; }
            int pi = (n * 2 + blockIdx.y) * 128 + Hi;   // 2048 partials
            if (MODE == 1) { g_psum0[pi] = s; g_psq0[pi] = q; }
            else           { g_psum1[pi] = s; g_psq1[pi] = q; }
        }
    }
}

// ---------------------------------------------------------------------------
// Cluster kernel: one CTA per group m (256 CTAs).
// ---------------------------------------------------------------------------
__global__ __launch_bounds__(256) void k_cluster(const float* __restrict__ alpha_p,
                                                 const float* __restrict__ beta_p) {
    __shared__ float cen[64][64];          // [c][s]
    __shared__ float ncS[64][34];          // [s][33] (+pad)
    __shared__ float svals[4096];
    __shared__ unsigned char sidx[4096];

    const int m = blockIdx.x;
    const int tid = threadIdx.x;
    const float* base = g_y + (long)m * 64 * 4096;
    const float alpha = *alpha_p, beta = *beta_p;

    // centers: mean over 8x8 block per (c, s)
#pragma unroll 1
    for (int it = 0; it < 16; it++) {
        int p = tid + it * 256;
        int c = p >> 6, s = p & 63;
        int a = s >> 3, bb = s & 7;
        const float* q = base + (c * 64 + a * 8) * 64 + bb * 8;
        float sum = 0.f;
#pragma unroll
        for (int hb = 0; hb < 8; hb++)
#pragma unroll
            for (int wd = 0; wd < 8; wd++) sum += q[hb * 64 + wd];
        cen[c][s] = sum * (1.0f / 64.0f);
    }
    __syncthreads();

    // normalize center point part (c<32), init scatter table from values
    if (tid < 64) {
        int s = tid;
        float ss = 0.f;
#pragma unroll
        for (int c = 0; c < 32; c++) { float v = cen[c][s]; ss += v * v; }
        float inv = 1.0f / fmaxf(sqrtf(ss), 1e-12f);
#pragma unroll
        for (int c = 0; c < 32; c++) cen[c][s] *= inv;
#pragma unroll
        for (int j = 0; j < 32; j++) ncS[s][j] = cen[32 + j][s];
        ncS[s][32] = 1.0f;
    }
    __syncthreads();

    // assignment + scatter
#pragma unroll 1
    for (int it = 0; it < 16; it++) {
        int l = tid + it * 256;
        float xp[32];
#pragma unroll
        for (int c = 0; c < 32; c++) xp[c] = base[c * 4096 + l];
        float ss = 0.f;
#pragma unroll
        for (int c = 0; c < 32; c++) ss += xp[c] * xp[c];
        float inv = 1.0f / fmaxf(sqrtf(ss), 1e-12f);

        float bestA = -3.4e38f; int bi = 0;
#pragma unroll 1
        for (int s4 = 0; s4 < 64; s4 += 4) {
            float ax = 0.f, ay = 0.f, az = 0.f, aw = 0.f;
#pragma unroll
            for (int c = 0; c < 32; c++) {
                float4 cs = *(const float4*)&cen[c][s4];
                ax += xp[c] * cs.x; ay += xp[c] * cs.y;
                az += xp[c] * cs.z; aw += xp[c] * cs.w;
            }
            float a0 = alpha * (ax * inv) + beta;
            float a1 = alpha * (ay * inv) + beta;
            float a2 = alpha * (az * inv) + beta;
            float a3 = alpha * (aw * inv) + beta;
            if (a0 > bestA) { bestA = a0; bi = s4;     }
            if (a1 > bestA) { bestA = a1; bi = s4 + 1; }
            if (a2 > bestA) { bestA = a2; bi = s4 + 2; }
            if (a3 > bestA) { bestA = a3; bi = s4 + 3; }
        }
        float val = 1.0f / (1.0f + expf(-bestA));
        svals[l] = val; sidx[l] = (unsigned char)bi;
#pragma unroll
        for (int j = 0; j < 32; j++) {
            float xv = base[(32 + j) * 4096 + l];
            atomicAdd(&ncS[bi][j], val * xv);
        }
        atomicAdd(&ncS[bi][32], val);
    }
    __syncthreads();

    if (tid < 64) {
        float r = 1.0f / ncS[tid][32];
#pragma unroll
        for (int j = 0; j < 32; j++) ncS[tid][j] *= r;
    }
    __syncthreads();

    // gather -> nx (NCHW, channel = fc*32 + j)
    const int fs2 = m & 1, fs1 = (m >> 1) & 1, fc = (m >> 2) & 7, n = m >> 5;
#pragma unroll 1
    for (int it = 0; it < 16; it++) {
        int l = tid + it * 256;
        int hp = l >> 6, wp = l & 63;
        float val = svals[l]; int bi = sidx[l];
        long ob = (((long)(n * 256 + fc * 32)) * 128 + (fs1 * 64 + hp)) * 128
                  + (fs2 * 64 + wp);
#pragma unroll
        for (int j = 0; j < 32; j++)
            g_nx[ob + (long)j * HW] = val * ncS[bi][j];
    }
}

// ------------------------- GN stats finalization ---------------------------
__global__ void k_stats0() {
    int n = threadIdx.x;
    if (n >= 8) return;
    float s = 0.f, q = 0.f;
    for (int i = n * 256; i < n * 256 + 256; i++) { s += g_psum0[i]; q += g_psq0[i]; }
    float mu = s / GN_COUNT;
    float var = fmaxf(q / GN_COUNT - mu * mu, 0.f);
    g_mu0[n] = mu; g_rs0[n] = rsqrtf(var + 1e-5f);
}
__global__ void k_stats1() {
    int n = threadIdx.x;
    if (n >= 8) return;
    float s = 0.f, q = 0.f;
    for (int i = n * 256; i < n * 256 + 256; i++) { s += g_psum1[i]; q += g_psq1[i]; }
    float mu = s / GN_COUNT;
    float var = fmaxf(q / GN_COUNT - mu * mu, 0.f);
    g_mu1[n] = mu; g_rs1[n] = rsqrtf(var + 1e-5f);
}

// ------------------- final: gn1 * layer_scale + residual -------------------
__global__ __launch_bounds__(256) void k_final(const float* __restrict__ x,
                                               const float* __restrict__ g1w,
                                               const float* __restrict__ g1b,
                                               const float* __restrict__ ls,
                                               float* __restrict__ out) {
    long i4 = (long)blockIdx.x * 256 + threadIdx.x;
    long i  = i4 * 4;
    int n = (int)(i >> 22);          // 256*16384 = 2^22
    int c = (int)((i >> 14) & 255);  // 16384 = 2^14
    float mu = g_mu1[n], rs = g_rs1[n];
    float gw = g1w[c] * ls[c];
    float sc = rs * gw;
    float sh = g1b[c] * ls[c] - mu * sc;
    float4 v  = *(const float4*)&g_out2[i];
    float4 xi = *(const float4*)&x[i];
    v.x = v.x * sc + sh + xi.x;
    v.y = v.y * sc + sh + xi.y;
    v.z = v.z * sc + sh + xi.z;
    v.w = v.w * sc + sh + xi.w;
    *(float4*)&out[i] = v;
}

// ---------------------------------------------------------------------------
extern "C" void kernel_launch(void* const* d_in, const int* in_sizes, int n_in,
                              void* d_out, int out_size) {
    const float* x       = (const float*)d_in[0];
    const float* proj_w  = (const float*)d_in[1];
    const float* proj_b  = (const float*)d_in[2];
    const float* merge_w = (const float*)d_in[3];
    const float* merge_b = (const float*)d_in[4];
    const float* alpha   = (const float*)d_in[5];
    const float* beta    = (const float*)d_in[6];
    const float* g0w     = (const float*)d_in[7];
    const float* g0b     = (const float*)d_in[8];
    const float* w0      = (const float*)d_in[9];
    const float* b0      = (const float*)d_in[10];
    const float* w1      = (const float*)d_in[11];
    const float* b1      = (const float*)d_in[12];
    const float* g1w     = (const float*)d_in[13];
    const float* g1b     = (const float*)d_in[14];
    const float* ls      = (const float*)d_in[15];
    float* out = (float*)d_out;

    // proj: 512x256 GEMM -> permuted cluster layout
    k_gemm<256, 0><<<dim3(128, 4, 8), 256>>>(x, proj_w, proj_b, nullptr, nullptr);
    // local clustering per group
    k_cluster<<<256, 256>>>(alpha, beta);
    // merge: 256x256 GEMM -> new_x (+ GN0 partials)
    k_gemm<256, 1><<<dim3(128, 2, 8), 256>>>(nullptr, merge_w, merge_b, nullptr, nullptr);
    k_stats0<<<1, 8>>>();
    // mlp0: concat(x, gn0(new_x)) @ W0 + b0, gelu -> hidden
    k_gemm<512, 2><<<dim3(128, 4, 8), 256>>>(x, w0, b0, g0w, g0b);
    // mlp1: hidden @ W1 + b1 -> out2 (+ GN1 partials)
    k_gemm<512, 3><<<dim3(128, 2, 8), 256>>>(nullptr, w1, b1, nullptr, nullptr);
    k_stats1<<<1, 8>>>();
    // gn1 * layer_scale + x
    k_final<<<32768, 256>>>(x, g1w, g1b, ls, out);
    (void)in_sizes; (void)n_in; (void)out_size;
}

// round 17
// speedup vs baseline: 2.4602x; 2.4602x over previous
#include <cuda_runtime.h>
#include <cuda_bf16.h>
#include <cstdint>
#include <math.h>

// ---------------------------------------------------------------------------
// x: (8, 256, 128, 128) fp32. proj -> 512ch -> cluster (m=256 groups of
// c=64 @ 64x64) -> merge -> 256ch -> GN -> MLP 512->512(gelu)->256 -> GN ->
// *layer_scale + x.  All GEMMs: bf16 HMMA (mma.sync m16n8k16), fp32 accum.
// ---------------------------------------------------------------------------
#define HW 16384
#define GN_COUNT 4194304.0f

// ------------------------- scratch (device globals) ------------------------
__device__ float g_y[256L * 64 * 64 * 64];
__device__ float g_nx[8L * 256 * 128 * 128];
__device__ float g_newx[8L * 256 * 128 * 128];
__device__ float g_th[8L * 512 * 128 * 128];
__device__ float g_out2[8L * 256 * 128 * 128];

__device__ float g_psum0[2048];
__device__ float g_psq0[2048];
__device__ float g_psum1[2048];
__device__ float g_psq1[2048];
__device__ float g_mu0[8];
__device__ float g_rs0[8];
__device__ float g_mu1[8];
__device__ float g_rs1[8];

// ------------------------- HMMA helpers ------------------------------------
__device__ __forceinline__ void ldsm4(uint32_t* r, const void* p) {
    uint32_t a = (uint32_t)__cvta_generic_to_shared(p);
    asm volatile("ldmatrix.sync.aligned.m8n8.x4.shared.b16 {%0,%1,%2,%3}, [%4];"
                 : "=r"(r[0]), "=r"(r[1]), "=r"(r[2]), "=r"(r[3]) : "r"(a));
}
__device__ __forceinline__ void ldsm4t(uint32_t* r, const void* p) {
    uint32_t a = (uint32_t)__cvta_generic_to_shared(p);
    asm volatile("ldmatrix.sync.aligned.m8n8.x4.trans.shared.b16 {%0,%1,%2,%3}, [%4];"
                 : "=r"(r[0]), "=r"(r[1]), "=r"(r[2]), "=r"(r[3]) : "r"(a));
}
__device__ __forceinline__ void mma16816(float* d, const uint32_t* a,
                                         uint32_t b0, uint32_t b1) {
    asm volatile(
        "mma.sync.aligned.m16n8k16.row.col.f32.bf16.bf16.f32 "
        "{%0,%1,%2,%3},{%4,%5,%6,%7},{%8,%9},{%0,%1,%2,%3};"
        : "+f"(d[0]), "+f"(d[1]), "+f"(d[2]), "+f"(d[3])
        : "r"(a[0]), "r"(a[1]), "r"(a[2]), "r"(a[3]), "r"(b0), "r"(b1));
}
__device__ __forceinline__ uint32_t pkbf(float x, float y) {
    __nv_bfloat162 t = __floats2bfloat162_rn(x, y);
    return *reinterpret_cast<uint32_t*>(&t);
}

// ---------------------------------------------------------------------------
// Tiled bf16-HMMA GEMM: out[o, p] = sum_k W[o,k] * X[k, p] + bias[o]
// CTA tile: 128 outputs x 128 pixels (one image row) x KT=32.
// 8 warps (2x4), warp tile 64x32.
// MODE 0: proj  (o-major W 512x256, X = x,               out -> g_y permuted)
// MODE 1: merge (o-major W 256x256, X = g_nx,            out -> g_newx + GN)
// MODE 2: mlp0  (k-major W 512x512, X = [x | gn0(newx)], out gelu -> g_th)
// MODE 3: mlp1  (k-major W 512x256, X = g_th,            out -> g_out2 + GN)
// ---------------------------------------------------------------------------
template <int KDIM, int MODE>
__global__ __launch_bounds__(256) void k_gemm(const float* __restrict__ B_in,
                                              const float* __restrict__ Wm,
                                              const float* __restrict__ bias,
                                              const float* __restrict__ aux0,
                                              const float* __restrict__ aux1) {
    constexpr bool AT  = (MODE >= 2);
    constexpr int  OD  = (MODE == 2) ? 512 : 256;
    constexpr int  ASZ = AT ? (32 * 136) : (128 * 40);
    constexpr int  NT  = KDIM / 32;

    __shared__ __nv_bfloat16 Asm[2][ASZ];
    __shared__ __nv_bfloat16 Bsm[2][32 * 136];
    __shared__ float rS[8];
    __shared__ float rQ[8];

    const int Hi = blockIdx.x;
    const int o0 = blockIdx.y * 128;
    const int nn = blockIdx.z;
    const int tid = threadIdx.x;
    const int lane = tid & 31;
    const int wid = tid >> 5;
    const int wm = (wid & 1) * 64;
    const int wn = (wid >> 1) * 32;
    const int rowoff = Hi * 128;

    float mu0 = 0.f, rs0 = 0.f;
    if (MODE == 2) { mu0 = g_mu0[nn]; rs0 = g_rs0[nn]; }

    float acc[4][4][4];
#pragma unroll
    for (int i = 0; i < 4; i++) {
#pragma unroll
        for (int j = 0; j < 4; j++) {
#pragma unroll
            for (int q = 0; q < 4; q++) { acc[i][j][q] = 0.f; }
        }
    }

    // per-thread global-load geometry
    const int a_o  = tid >> 1;               // non-AT: output row
    const int a_kh = (tid & 1) * 16;         // non-AT: k half
    const int r_kk  = tid >> 3;              // AT + B: k row
    const int r_seg = (tid & 7) * 16;        // AT + B: 16-elem segment

    float4 ra[4];
    float4 rb[4];

    for (int t = 0; t < NT; t++) {
        const int c0 = t * 32;
        // ---- global loads into registers ----
        if (!AT) {
            const float* p = Wm + (long)(o0 + a_o) * KDIM + c0 + a_kh;
#pragma unroll
            for (int j = 0; j < 4; j++) { ra[j] = *(const float4*)(p + j * 4); }
        } else {
            const float* p = Wm + (long)(c0 + r_kk) * OD + o0 + r_seg;
#pragma unroll
            for (int j = 0; j < 4; j++) { ra[j] = *(const float4*)(p + j * 4); }
        }
        {
            const int ch = c0 + r_kk;
            const float* p;
            if (MODE == 0) {
                p = B_in + (long)(nn * 256 + ch) * HW + rowoff + r_seg;
            } else if (MODE == 1) {
                p = g_nx + (long)(nn * 256 + ch) * HW + rowoff + r_seg;
            } else if (MODE == 3) {
                p = g_th + (long)(nn * 512 + ch) * HW + rowoff + r_seg;
            } else {
                if (ch < 256) {
                    p = B_in + (long)(nn * 256 + ch) * HW + rowoff + r_seg;
                } else {
                    p = g_newx + (long)(nn * 256 + (ch - 256)) * HW + rowoff + r_seg;
                }
            }
#pragma unroll
            for (int j = 0; j < 4; j++) { rb[j] = *(const float4*)(p + j * 4); }
            if (MODE == 2 && ch >= 256) {
                const int cc = ch - 256;
                const float sc = rs0 * aux0[cc];
                const float sh = aux1[cc] - mu0 * sc;
#pragma unroll
                for (int j = 0; j < 4; j++) {
                    rb[j].x = rb[j].x * sc + sh;
                    rb[j].y = rb[j].y * sc + sh;
                    rb[j].z = rb[j].z * sc + sh;
                    rb[j].w = rb[j].w * sc + sh;
                }
            }
        }
        // ---- stage to SMEM (bf16) ----
        const int buf = t & 1;
        {
            uint32_t u[8];
#pragma unroll
            for (int j = 0; j < 4; j++) {
                u[2 * j]     = pkbf(ra[j].x, ra[j].y);
                u[2 * j + 1] = pkbf(ra[j].z, ra[j].w);
            }
            int off;
            if (!AT) { off = a_o * 40 + a_kh; } else { off = r_kk * 136 + r_seg; }
            *(uint4*)&Asm[buf][off]     = make_uint4(u[0], u[1], u[2], u[3]);
            *(uint4*)&Asm[buf][off + 8] = make_uint4(u[4], u[5], u[6], u[7]);
        }
        {
            uint32_t u[8];
#pragma unroll
            for (int j = 0; j < 4; j++) {
                u[2 * j]     = pkbf(rb[j].x, rb[j].y);
                u[2 * j + 1] = pkbf(rb[j].z, rb[j].w);
            }
            const int off = r_kk * 136 + r_seg;
            *(uint4*)&Bsm[buf][off]     = make_uint4(u[0], u[1], u[2], u[3]);
            *(uint4*)&Bsm[buf][off + 8] = make_uint4(u[4], u[5], u[6], u[7]);
        }
        __syncthreads();
        // ---- compute on this tile ----
#pragma unroll
        for (int ks = 0; ks < 2; ks++) {
            const int k0 = ks * 16;
            uint32_t af[4][4];
            if (!AT) {
                const int row  = wm + (lane & 15);
                const int coff = k0 + (lane >> 4) * 8;
#pragma unroll
                for (int mf = 0; mf < 4; mf++) {
                    ldsm4(af[mf], &Asm[buf][(row + mf * 16) * 40 + coff]);
                }
            } else {
                const int kr = k0 + (lane & 7) + ((lane & 16) ? 8 : 0);
                const int cb = wm + ((lane & 8) ? 8 : 0);
#pragma unroll
                for (int mf = 0; mf < 4; mf++) {
                    ldsm4t(af[mf], &Asm[buf][kr * 136 + cb + mf * 16]);
                }
            }
            uint32_t bf0[4];
            uint32_t bf1[4];
            {
                const int kr = k0 + (lane & 7) + ((lane & 8) ? 8 : 0);
                const int cb = wn + ((lane & 16) ? 8 : 0);
                ldsm4t(bf0, &Bsm[buf][kr * 136 + cb]);
                ldsm4t(bf1, &Bsm[buf][kr * 136 + cb + 16]);
            }
#pragma unroll
            for (int mf = 0; mf < 4; mf++) {
                mma16816(acc[mf][0], af[mf], bf0[0], bf0[1]);
                mma16816(acc[mf][1], af[mf], bf0[2], bf0[3]);
                mma16816(acc[mf][2], af[mf], bf1[0], bf1[1]);
                mma16816(acc[mf][3], af[mf], bf1[2], bf1[3]);
            }
        }
        __syncthreads();
    }

    // ---- epilogue ----
    const int qrow = lane >> 2;
    const int qcol = (lane & 3) * 2;
    float lsum = 0.f, lsq = 0.f;
#pragma unroll
    for (int mf = 0; mf < 4; mf++) {
#pragma unroll
        for (int half = 0; half < 2; half++) {
            const int o = o0 + wm + mf * 16 + qrow + half * 8;
            const float bv = bias[o];
#pragma unroll
            for (int nf = 0; nf < 4; nf++) {
                const int w0c = wn + nf * 8 + qcol;
                const float v0 = acc[mf][nf][half * 2 + 0] + bv;
                const float v1 = acc[mf][nf][half * 2 + 1] + bv;
                if (MODE == 0) {
                    const int fc = o >> 6, cp = o & 63;
                    const int fs1 = Hi >> 6, hp = Hi & 63;
                    const long m2 = (long)(((nn * 8 + fc) * 2 + fs1) * 2);
                    const long cb = (m2 * 64 + cp) * 4096 + hp * 64;
                    {
                        const int fs2a = w0c >> 6, wpa = w0c & 63;
                        g_y[cb + (long)fs2a * 262144 + wpa] = v0;
                        const int fs2b = (w0c + 1) >> 6, wpb = (w0c + 1) & 63;
                        g_y[cb + (long)fs2b * 262144 + wpb] = v1;
                    }
                } else if (MODE == 1) {
                    const long base = (long)(nn * 256 + o) * HW + rowoff + w0c;
                    *(float2*)&g_newx[base] = make_float2(v0, v1);
                    lsum += v0 + v1;
                    lsq  += v0 * v0 + v1 * v1;
                } else if (MODE == 2) {
                    const float g0 = 0.5f * v0 * (1.0f + erff(v0 * 0.70710678f));
                    const float g1 = 0.5f * v1 * (1.0f + erff(v1 * 0.70710678f));
                    const long base = (long)(nn * 512 + o) * HW + rowoff + w0c;
                    *(float2*)&g_th[base] = make_float2(g0, g1);
                } else {
                    const long base = (long)(nn * 256 + o) * HW + rowoff + w0c;
                    *(float2*)&g_out2[base] = make_float2(v0, v1);
                    lsum += v0 + v1;
                    lsq  += v0 * v0 + v1 * v1;
                }
            }
        }
    }
    if (MODE == 1 || MODE == 3) {
#pragma unroll
        for (int off = 16; off; off >>= 1) {
            lsum += __shfl_down_sync(0xffffffffu, lsum, off);
            lsq  += __shfl_down_sync(0xffffffffu, lsq,  off);
        }
        if (lane == 0) { rS[wid] = lsum; rQ[wid] = lsq; }
        __syncthreads();
        if (tid == 0) {
            float s = 0.f, q = 0.f;
#pragma unroll
            for (int i = 0; i < 8; i++) { s += rS[i]; q += rQ[i]; }
            const int pi = (nn * 2 + blockIdx.y) * 128 + Hi;
            if (MODE == 1) { g_psum0[pi] = s; g_psq0[pi] = q; }
            else           { g_psum1[pi] = s; g_psq1[pi] = q; }
        }
    }
}

// ---------------------------------------------------------------------------
// Cluster kernel: one CTA per group m (256 CTAs).
// ---------------------------------------------------------------------------
__global__ __launch_bounds__(256) void k_cluster(const float* __restrict__ alpha_p,
                                                 const float* __restrict__ beta_p) {
    __shared__ float cen[64][64];
    __shared__ float ncS[64][34];
    __shared__ float svals[4096];
    __shared__ unsigned char sidx[4096];

    const int m = blockIdx.x;
    const int tid = threadIdx.x;
    const float* base = g_y + (long)m * 64 * 4096;
    const float alpha = *alpha_p;
    const float beta  = *beta_p;

    // centers: mean over each 8x8 block, per channel
#pragma unroll 1
    for (int it = 0; it < 16; it++) {
        const int p = tid + it * 256;
        const int c = p >> 6, s = p & 63;
        const int a = s >> 3, b = s & 7;
        const float* q = base + (c * 64 + a * 8) * 64 + b * 8;
        float sum = 0.f;
#pragma unroll
        for (int hb = 0; hb < 8; hb++) {
#pragma unroll
            for (int wd = 0; wd < 8; wd++) { sum += q[hb * 64 + wd]; }
        }
        cen[c][s] = sum * (1.0f / 64.0f);
    }
    __syncthreads();

    // normalize center point half; init scatter table from center values
    if (tid < 64) {
        const int s = tid;
        float ss = 0.f;
#pragma unroll
        for (int c = 0; c < 32; c++) { const float v = cen[c][s]; ss += v * v; }
        const float inv = 1.0f / fmaxf(sqrtf(ss), 1e-12f);
#pragma unroll
        for (int c = 0; c < 32; c++) { cen[c][s] *= inv; }
#pragma unroll
        for (int j = 0; j < 32; j++) { ncS[s][j] = cen[32 + j][s]; }
        ncS[s][32] = 1.0f;
    }
    __syncthreads();

    // assignment + scatter
#pragma unroll 1
    for (int it = 0; it < 16; it++) {
        const int l = tid + it * 256;
        float xp[32];
#pragma unroll
        for (int c = 0; c < 32; c++) { xp[c] = base[c * 4096 + l]; }
        float ss = 0.f;
#pragma unroll
        for (int c = 0; c < 32; c++) { ss += xp[c] * xp[c]; }
        const float inv = 1.0f / fmaxf(sqrtf(ss), 1e-12f);

        float bestA = -3.4e38f;
        int bi = 0;
#pragma unroll 1
        for (int s4 = 0; s4 < 64; s4 += 4) {
            float ax = 0.f, ay = 0.f, az = 0.f, aw = 0.f;
#pragma unroll
            for (int c = 0; c < 32; c++) {
                const float4 cs = *(const float4*)&cen[c][s4];
                ax += xp[c] * cs.x;
                ay += xp[c] * cs.y;
                az += xp[c] * cs.z;
                aw += xp[c] * cs.w;
            }
            const float a0 = alpha * (ax * inv) + beta;
            const float a1 = alpha * (ay * inv) + beta;
            const float a2 = alpha * (az * inv) + beta;
            const float a3 = alpha * (aw * inv) + beta;
            if (a0 > bestA) { bestA = a0; bi = s4; }
            if (a1 > bestA) { bestA = a1; bi = s4 + 1; }
            if (a2 > bestA) { bestA = a2; bi = s4 + 2; }
            if (a3 > bestA) { bestA = a3; bi = s4 + 3; }
        }
        const float val = 1.0f / (1.0f + expf(-bestA));
        svals[l] = val;
        sidx[l] = (unsigned char)bi;
#pragma unroll
        for (int j = 0; j < 32; j++) {
            const float xv = base[(32 + j) * 4096 + l];
            atomicAdd(&ncS[bi][j], val * xv);
        }
        atomicAdd(&ncS[bi][32], val);
    }
    __syncthreads();

    if (tid < 64) {
        const float r = 1.0f / ncS[tid][32];
#pragma unroll
        for (int j = 0; j < 32; j++) { ncS[tid][j] *= r; }
    }
    __syncthreads();

    // gather -> g_nx (NCHW, channel = fc*32 + j)
    const int fs2 = m & 1;
    const int fs1 = (m >> 1) & 1;
    const int fc  = (m >> 2) & 7;
    const int n   = m >> 5;
#pragma unroll 1
    for (int it = 0; it < 16; it++) {
        const int l = tid + it * 256;
        const int hp = l >> 6, wp = l & 63;
        const float val = svals[l];
        const int bi = sidx[l];
        const long ob = (((long)(n * 256 + fc * 32)) * 128 + (fs1 * 64 + hp)) * 128
                        + (fs2 * 64 + wp);
#pragma unroll
        for (int j = 0; j < 32; j++) {
            g_nx[ob + (long)j * HW] = val * ncS[bi][j];
        }
    }
}

// ------------------------- GN stats finalization ---------------------------
__global__ void k_stats0() {
    const int n = threadIdx.x;
    if (n >= 8) return;
    float s = 0.f, q = 0.f;
    for (int i = n * 256; i < n * 256 + 256; i++) { s += g_psum0[i]; q += g_psq0[i]; }
    const float mu = s / GN_COUNT;
    const float var = fmaxf(q / GN_COUNT - mu * mu, 0.f);
    g_mu0[n] = mu;
    g_rs0[n] = rsqrtf(var + 1e-5f);
}
__global__ void k_stats1() {
    const int n = threadIdx.x;
    if (n >= 8) return;
    float s = 0.f, q = 0.f;
    for (int i = n * 256; i < n * 256 + 256; i++) { s += g_psum1[i]; q += g_psq1[i]; }
    const float mu = s / GN_COUNT;
    const float var = fmaxf(q / GN_COUNT - mu * mu, 0.f);
    g_mu1[n] = mu;
    g_rs1[n] = rsqrtf(var + 1e-5f);
}

// ------------------- final: gn1 * layer_scale + residual -------------------
__global__ __launch_bounds__(256) void k_final(const float* __restrict__ x,
                                               const float* __restrict__ g1w,
                                               const float* __restrict__ g1b,
                                               const float* __restrict__ ls,
                                               float* __restrict__ out) {
    const long i = ((long)blockIdx.x * 256 + threadIdx.x) * 4;
    const int n = (int)(i >> 22);
    const int c = (int)((i >> 14) & 255);
    const float mu = g_mu1[n];
    const float rs = g_rs1[n];
    const float gw = g1w[c] * ls[c];
    const float sc = rs * gw;
    const float sh = g1b[c] * ls[c] - mu * sc;
    float4 v        = *(const float4*)&g_out2[i];
    const float4 xi = *(const float4*)&x[i];
    v.x = v.x * sc + sh + xi.x;
    v.y = v.y * sc + sh + xi.y;
    v.z = v.z * sc + sh + xi.z;
    v.w = v.w * sc + sh + xi.w;
    *(float4*)&out[i] = v;
}

// ---------------------------------------------------------------------------
extern "C" void kernel_launch(void* const* d_in, const int* in_sizes, int n_in,
                              void* d_out, int out_size) {
    const float* x       = (const float*)d_in[0];
    const float* proj_w  = (const float*)d_in[1];
    const float* proj_b  = (const float*)d_in[2];
    const float* merge_w = (const float*)d_in[3];
    const float* merge_b = (const float*)d_in[4];
    const float* alpha   = (const float*)d_in[5];
    const float* beta    = (const float*)d_in[6];
    const float* g0w     = (const float*)d_in[7];
    const float* g0b     = (const float*)d_in[8];
    const float* w0      = (const float*)d_in[9];
    const float* b0      = (const float*)d_in[10];
    const float* w1      = (const float*)d_in[11];
    const float* b1      = (const float*)d_in[12];
    const float* g1w     = (const float*)d_in[13];
    const float* g1b     = (const float*)d_in[14];
    const float* ls      = (const float*)d_in[15];
    float* out = (float*)d_out;

    k_gemm<256, 0><<<dim3(128, 4, 8), 256>>>(x, proj_w, proj_b, 0, 0);
    k_cluster<<<256, 256>>>(alpha, beta);
    k_gemm<256, 1><<<dim3(128, 2, 8), 256>>>(0, merge_w, merge_b, 0, 0);
    k_stats0<<<1, 8>>>();
    k_gemm<512, 2><<<dim3(128, 4, 8), 256>>>(x, w0, b0, g0w, g0b);
    k_gemm<512, 3><<<dim3(128, 2, 8), 256>>>(0, w1, b1, 0, 0);
    k_stats1<<<1, 8>>>();
    k_final<<<32768, 256>>>(x, g1w, g1b, ls, out);
    (void)in_sizes; (void)n_in; (void)out_size;
}